// round 15
// baseline (speedup 1.0000x reference)
#include <cuda_runtime.h>

// MFELoss: softmax over C=4, masked squared-error reduction to a scalar.
// HBM-bound streaming reduction: 128 MiB preds (fp32) + 32 MiB target (int32).
// R15: software-pipelined loop — issue iteration k+1's loads BEFORE computing
// iteration k, so every warp always has loads in flight (fixes the
// issue->wait->compute serialization seen as occ=100%, issue=32%, DRAM=60%).
// 2 rows/iter keeps regs ~36 -> 7 CTAs/SM, one exact wave of 1064 blocks.

#define NBLK 1064   // 152 SMs x 7 CTAs
#define NTHR 256

// Per-block partials: [0]=fne_sum, [1]=fpe_sum, [2]=fne_count
static __device__ float g_part[NBLK][3];
static __device__ unsigned int g_ticket = 0;   // reset to 0 by last block each launch

__device__ __forceinline__ float rcp_fast(float x) {
    float r;
    asm("rcp.approx.f32 %0, %1;" : "=f"(r) : "f"(x));
    return r;
}

#define LOG2E 1.4426950408889634f

// OI compile-time:  p_o = 1 / (1 + sum_{j!=OI} exp2(r_j*L - r_o*L))
// fne_i = (1-p_o)^2 on target==OI rows, fpe_i = p_o^2 otherwise.
template <int OI>
__device__ __forceinline__ void accum_row_t(float4 r, int t,
                                            float& fne, float& fpe, float& cnt) {
    float ro  = (OI == 0) ? r.x : (OI == 1) ? r.y : (OI == 2) ? r.z : r.w;
    float nroL = -ro * LOG2E;
    float s = 1.0f;
    if (OI != 0) s += exp2f(fmaf(r.x, LOG2E, nroL));
    if (OI != 1) s += exp2f(fmaf(r.y, LOG2E, nroL));
    if (OI != 2) s += exp2f(fmaf(r.z, LOG2E, nroL));
    if (OI != 3) s += exp2f(fmaf(r.w, LOG2E, nroL));
    float po = rcp_fast(s);
    float d  = 1.0f - po;
    if (t == OI) { fne += d * d; cnt += 1.0f; }
    else         { fpe += po * po; }
}

template <int OI>
__device__ __forceinline__ void reduce_loop(const float4* __restrict__ preds,
                                            const int2*   __restrict__ tgt2,
                                            int n_pairs,
                                            float& fne, float& fpe, float& cnt) {
    float fneA = 0.0f, fpeA = 0.0f, cntA = 0.0f;
    float fneB = 0.0f, fpeB = 0.0f, cntB = 0.0f;

    const int stride = gridDim.x * blockDim.x;
    int i = blockIdx.x * blockDim.x + threadIdx.x;

    // Prologue: load first batch.
    float4 c0, c1;
    int2   ct;
    bool have = (i < n_pairs);
    if (have) {
        c0 = preds[2 * i + 0];
        c1 = preds[2 * i + 1];
        ct = tgt2[i];
    }

    while (have) {
        // Issue NEXT batch's loads first (predicated; in flight during compute).
        int  j      = i + stride;
        bool have_n = (j < n_pairs);
        float4 n0, n1;
        int2   nt;
        if (have_n) {
            n0 = preds[2 * j + 0];
            n1 = preds[2 * j + 1];
            nt = tgt2[j];
        }

        // Compute current batch while next loads are outstanding.
        accum_row_t<OI>(c0, ct.x, fneA, fpeA, cntA);
        accum_row_t<OI>(c1, ct.y, fneB, fpeB, cntB);

        c0 = n0; c1 = n1; ct = nt;
        i = j; have = have_n;
    }

    fne = fneA + fneB;
    fpe = fpeA + fpeB;
    cnt = cntA + cntB;
}

__global__ void __launch_bounds__(NTHR, 7)
mfe_fused_kernel(const float4* __restrict__ preds,   // [B] rows of 4 floats
                 const int2*   __restrict__ tgt2,    // [B/2] pairs of int32
                 const int*    __restrict__ oi_ptr,
                 int n_pairs,                        // B/2
                 float n_total,                      // B
                 float* __restrict__ out)
{
    const int oi = *oi_ptr;   // runtime-uniform; dispatch once
    float fne, fpe, cnt;

    switch (oi) {
        case 0:  reduce_loop<0>(preds, tgt2, n_pairs, fne, fpe, cnt); break;
        case 1:  reduce_loop<1>(preds, tgt2, n_pairs, fne, fpe, cnt); break;
        case 2:  reduce_loop<2>(preds, tgt2, n_pairs, fne, fpe, cnt); break;
        default: reduce_loop<3>(preds, tgt2, n_pairs, fne, fpe, cnt); break;
    }

    // ---- intra-block reduce ----
    #pragma unroll
    for (int off = 16; off > 0; off >>= 1) {
        fne += __shfl_down_sync(0xFFFFFFFFu, fne, off);
        fpe += __shfl_down_sync(0xFFFFFFFFu, fpe, off);
        cnt += __shfl_down_sync(0xFFFFFFFFu, cnt, off);
    }
    __shared__ float s_fne[NTHR / 32];
    __shared__ float s_fpe[NTHR / 32];
    __shared__ float s_cnt[NTHR / 32];
    int lane = threadIdx.x & 31;
    int wid  = threadIdx.x >> 5;
    if (lane == 0) { s_fne[wid] = fne; s_fpe[wid] = fpe; s_cnt[wid] = cnt; }
    __syncthreads();
    if (threadIdx.x < 32) {
        float f = (lane < NTHR / 32) ? s_fne[lane] : 0.0f;
        float p = (lane < NTHR / 32) ? s_fpe[lane] : 0.0f;
        float c = (lane < NTHR / 32) ? s_cnt[lane] : 0.0f;
        #pragma unroll
        for (int off = 4; off > 0; off >>= 1) {
            f += __shfl_down_sync(0xFFFFFFFFu, f, off);
            p += __shfl_down_sync(0xFFFFFFFFu, p, off);
            c += __shfl_down_sync(0xFFFFFFFFu, c, off);
        }
        if (lane == 0) {
            g_part[blockIdx.x][0] = f;
            g_part[blockIdx.x][1] = p;
            g_part[blockIdx.x][2] = c;
        }
    }

    // ---- last-block finalize ----
    __shared__ bool s_is_last;
    __threadfence();                 // release: g_part writes visible chip-wide
    __syncthreads();
    if (threadIdx.x == 0) {
        unsigned int ticket = atomicAdd(&g_ticket, 1u);
        s_is_last = (ticket == (unsigned int)(gridDim.x - 1));
    }
    __syncthreads();
    if (!s_is_last) return;

    __threadfence();                 // acquire: see all blocks' partials

    double dfne = 0.0, dfpe = 0.0, dcnt = 0.0;
    for (int i2 = threadIdx.x; i2 < NBLK; i2 += NTHR) {
        dfne += (double)g_part[i2][0];
        dfpe += (double)g_part[i2][1];
        dcnt += (double)g_part[i2][2];
    }
    #pragma unroll
    for (int off = 16; off > 0; off >>= 1) {
        dfne += __shfl_down_sync(0xFFFFFFFFu, dfne, off);
        dfpe += __shfl_down_sync(0xFFFFFFFFu, dfpe, off);
        dcnt += __shfl_down_sync(0xFFFFFFFFu, dcnt, off);
    }
    __shared__ double s_f[NTHR / 32], s_p[NTHR / 32], s_c[NTHR / 32];
    if (lane == 0) { s_f[wid] = dfne; s_p[wid] = dfpe; s_c[wid] = dcnt; }
    __syncthreads();
    if (threadIdx.x == 0) {
        double F = 0.0, P = 0.0, Cn = 0.0;
        #pragma unroll
        for (int w = 0; w < NTHR / 32; w++) { F += s_f[w]; P += s_p[w]; Cn += s_c[w]; }
        float fne_num = (float)Cn;
        float fpe_num = n_total - fne_num;
        out[0] = (float)(P / (double)fpe_num + F / (double)fne_num);
        __threadfence();
        g_ticket = 0;                // deterministic reset for next graph replay
    }
}

extern "C" void kernel_launch(void* const* d_in, const int* in_sizes, int n_in,
                              void* d_out, int out_size)
{
    const float4* preds  = (const float4*)d_in[0];
    const int2*   tgt2   = (const int2*)d_in[1];
    const int*    oi_ptr = (const int*)d_in[2];
    float*        out    = (float*)d_out;

    int n_rows  = in_sizes[0] / 4;     // B
    int n_pairs = n_rows / 2;

    mfe_fused_kernel<<<NBLK, NTHR>>>(preds, tgt2, oi_ptr, n_pairs, (float)n_rows, out);
}

// round 16
// speedup vs baseline: 1.0049x; 1.0049x over previous
#include <cuda_runtime.h>
#include <cstdint>

// MFELoss: softmax over C=4, masked squared-error reduction to a scalar.
// HBM-bound streaming reduction: 128 MiB preds (fp32) + 32 MiB target (int32).
// R16: LDG-based variants all plateau at ~4.8 TB/s (per-SM outstanding-line
// tracking cap on register-destination loads). Switch mechanism: cp.async.bulk
// (TMA/UBLKCP) stages 10KB/stage into a 3-deep SMEM ring per CTA; in-flight
// tracked by mbarrier tx-count, not load scoreboard -> ~140KB/SM in flight.
// Compute from SMEM. One exact wave: 152 SMs x 7 CTAs (30KB smem/CTA).

#define NBLK 1064          // 152 x 7
#define NTHR 256
#define NSTAGE 3
#define ROWS_PER_STAGE 512 // preds 8KB + tgt 2KB = 10KB per stage

// Per-block partials: [0]=fne_sum, [1]=fpe_sum, [2]=fne_count
static __device__ float g_part[NBLK][3];
static __device__ unsigned int g_ticket = 0;   // reset to 0 by last block each launch

__device__ __forceinline__ float rcp_fast(float x) {
    float r;
    asm("rcp.approx.f32 %0, %1;" : "=f"(r) : "f"(x));
    return r;
}

#define LOG2E 1.4426950408889634f

// OI compile-time: p_o = 1 / (1 + sum_{j!=OI} exp2((r_j - r_o)*log2e))
// fne_i = (1-p_o)^2 on target==OI rows, fpe_i = p_o^2 otherwise.
template <int OI>
__device__ __forceinline__ void accum_row_t(float4 r, int t,
                                            float& fne, float& fpe, float& cnt) {
    float ro   = (OI == 0) ? r.x : (OI == 1) ? r.y : (OI == 2) ? r.z : r.w;
    float nroL = -ro * LOG2E;
    float s = 1.0f;
    if (OI != 0) s += exp2f(fmaf(r.x, LOG2E, nroL));
    if (OI != 1) s += exp2f(fmaf(r.y, LOG2E, nroL));
    if (OI != 2) s += exp2f(fmaf(r.z, LOG2E, nroL));
    if (OI != 3) s += exp2f(fmaf(r.w, LOG2E, nroL));
    float po = rcp_fast(s);
    float d  = 1.0f - po;
    if (t == OI) { fne += d * d; cnt += 1.0f; }
    else         { fpe += po * po; }
}

__device__ __forceinline__ void mbar_wait(uint32_t mb, uint32_t phase) {
    asm volatile(
        "{\n\t"
        ".reg .pred P;\n\t"
        "W%=:\n\t"
        "mbarrier.try_wait.parity.acquire.cta.shared::cta.b64 P, [%0], %1, 0x989680;\n\t"
        "@P bra D%=;\n\t"
        "bra W%=;\n\t"
        "D%=:\n\t"
        "}"
        :: "r"(mb), "r"(phase) : "memory");
}

// Shared state lives at kernel scope; the templated body does all work.
template <int OI>
__device__ __forceinline__ void mfe_body(const float4* __restrict__ preds,
                                         const int*    __restrict__ tgt,
                                         int n_rows, int S, float n_total,
                                         float* __restrict__ out,
                                         float4 (&sp)[NSTAGE][ROWS_PER_STAGE],
                                         int    (&st_)[NSTAGE][ROWS_PER_STAGE],
                                         unsigned long long (&mbar)[NSTAGE])
{
    const uint32_t sp_base = (uint32_t)__cvta_generic_to_shared(&sp[0][0]);
    const uint32_t st_base = (uint32_t)__cvta_generic_to_shared(&st_[0][0]);
    const uint32_t mb_base = (uint32_t)__cvta_generic_to_shared(&mbar[0]);
    const int tid = threadIdx.x;

    if (tid == 0) {
        #pragma unroll
        for (int k = 0; k < NSTAGE; k++)
            asm volatile("mbarrier.init.shared.b64 [%0], 1;"
                         :: "r"(mb_base + k * 8) : "memory");
    }
    __syncthreads();

    auto issue_stage = [&](int s) {
        if (s >= S) return;
        long long rb = ((long long)s * gridDim.x + blockIdx.x) * ROWS_PER_STAGE;
        long long rem = (long long)n_rows - rb;
        if (rem <= 0) return;
        int valid = rem < ROWS_PER_STAGE ? (int)rem : ROWS_PER_STAGE;
        if (tid == 0) {
            int b = s % NSTAGE;
            uint32_t mb = mb_base + b * 8;
            uint32_t pbytes = (uint32_t)valid * 16u;
            uint32_t tbytes = (((uint32_t)valid * 4u) + 15u) & ~15u;
            asm volatile("mbarrier.arrive.expect_tx.shared.b64 _, [%0], %1;"
                         :: "r"(mb), "r"(pbytes + tbytes) : "memory");
            asm volatile("cp.async.bulk.shared::cta.global.mbarrier::complete_tx::bytes "
                         "[%0], [%1], %2, [%3];"
                         :: "r"(sp_base + (uint32_t)b * (ROWS_PER_STAGE * 16u)),
                            "l"(preds + rb), "r"(pbytes), "r"(mb) : "memory");
            asm volatile("cp.async.bulk.shared::cta.global.mbarrier::complete_tx::bytes "
                         "[%0], [%1], %2, [%3];"
                         :: "r"(st_base + (uint32_t)b * (ROWS_PER_STAGE * 4u)),
                            "l"(tgt + rb), "r"(tbytes), "r"(mb) : "memory");
        }
    };

    issue_stage(0);
    issue_stage(1);

    float fneA = 0.0f, fpeA = 0.0f, cntA = 0.0f;
    float fneB = 0.0f, fpeB = 0.0f, cntB = 0.0f;

    for (int s = 0; s < S; s++) {
        long long rb = ((long long)s * gridDim.x + blockIdx.x) * ROWS_PER_STAGE;
        long long rem = (long long)n_rows - rb;
        int b = s % NSTAGE;
        if (rem > 0) {
            int valid = rem < ROWS_PER_STAGE ? (int)rem : ROWS_PER_STAGE;
            mbar_wait(mb_base + (uint32_t)b * 8u, (uint32_t)((s / NSTAGE) & 1));
            if (tid < valid) {
                float4 r0 = sp[b][tid];
                int    t0 = st_[b][tid];
                accum_row_t<OI>(r0, t0, fneA, fpeA, cntA);
            }
            if (tid + 256 < valid) {
                float4 r1 = sp[b][tid + 256];
                int    t1 = st_[b][tid + 256];
                accum_row_t<OI>(r1, t1, fneB, fpeB, cntB);
            }
        }
        __syncthreads();           // buffer-reuse fence before overwriting ring slot
        issue_stage(s + 2);
    }

    float fne = fneA + fneB;
    float fpe = fpeA + fpeB;
    float cnt = cntA + cntB;

    // ---- intra-block reduce ----
    #pragma unroll
    for (int off = 16; off > 0; off >>= 1) {
        fne += __shfl_down_sync(0xFFFFFFFFu, fne, off);
        fpe += __shfl_down_sync(0xFFFFFFFFu, fpe, off);
        cnt += __shfl_down_sync(0xFFFFFFFFu, cnt, off);
    }
    __shared__ float s_fne[NTHR / 32];
    __shared__ float s_fpe[NTHR / 32];
    __shared__ float s_cnt[NTHR / 32];
    int lane = tid & 31;
    int wid  = tid >> 5;
    if (lane == 0) { s_fne[wid] = fne; s_fpe[wid] = fpe; s_cnt[wid] = cnt; }
    __syncthreads();
    if (tid < 32) {
        float f = (lane < NTHR / 32) ? s_fne[lane] : 0.0f;
        float p = (lane < NTHR / 32) ? s_fpe[lane] : 0.0f;
        float c = (lane < NTHR / 32) ? s_cnt[lane] : 0.0f;
        #pragma unroll
        for (int off = 4; off > 0; off >>= 1) {
            f += __shfl_down_sync(0xFFFFFFFFu, f, off);
            p += __shfl_down_sync(0xFFFFFFFFu, p, off);
            c += __shfl_down_sync(0xFFFFFFFFu, c, off);
        }
        if (lane == 0) {
            g_part[blockIdx.x][0] = f;
            g_part[blockIdx.x][1] = p;
            g_part[blockIdx.x][2] = c;
        }
    }

    // ---- last-block finalize ----
    __shared__ bool s_is_last;
    __threadfence();
    __syncthreads();
    if (tid == 0) {
        unsigned int ticket = atomicAdd(&g_ticket, 1u);
        s_is_last = (ticket == (unsigned int)(gridDim.x - 1));
    }
    __syncthreads();
    if (!s_is_last) return;

    __threadfence();

    double dfne = 0.0, dfpe = 0.0, dcnt = 0.0;
    for (int i = tid; i < NBLK; i += NTHR) {
        dfne += (double)g_part[i][0];
        dfpe += (double)g_part[i][1];
        dcnt += (double)g_part[i][2];
    }
    #pragma unroll
    for (int off = 16; off > 0; off >>= 1) {
        dfne += __shfl_down_sync(0xFFFFFFFFu, dfne, off);
        dfpe += __shfl_down_sync(0xFFFFFFFFu, dfpe, off);
        dcnt += __shfl_down_sync(0xFFFFFFFFu, dcnt, off);
    }
    __shared__ double s_f[NTHR / 32], s_p[NTHR / 32], s_c[NTHR / 32];
    if (lane == 0) { s_f[wid] = dfne; s_p[wid] = dfpe; s_c[wid] = dcnt; }
    __syncthreads();
    if (tid == 0) {
        double F = 0.0, P = 0.0, Cn = 0.0;
        #pragma unroll
        for (int w = 0; w < NTHR / 32; w++) { F += s_f[w]; P += s_p[w]; Cn += s_c[w]; }
        float fne_num = (float)Cn;
        float fpe_num = n_total - fne_num;
        out[0] = (float)(P / (double)fpe_num + F / (double)fne_num);
        __threadfence();
        g_ticket = 0;                // deterministic reset for next graph replay
    }
}

__global__ void __launch_bounds__(NTHR)
mfe_tma_kernel(const float4* __restrict__ preds, const int* __restrict__ tgt,
               const int* __restrict__ oi_ptr, int n_rows, int S,
               float n_total, float* __restrict__ out)
{
    __shared__ float4 sp[NSTAGE][ROWS_PER_STAGE];       // 24KB
    __shared__ int    st_[NSTAGE][ROWS_PER_STAGE];      // 6KB
    __shared__ unsigned long long mbar[NSTAGE];

    const int oi = *oi_ptr;   // uniform; one specialized path executes
    switch (oi) {
        case 0:  mfe_body<0>(preds, tgt, n_rows, S, n_total, out, sp, st_, mbar); break;
        case 1:  mfe_body<1>(preds, tgt, n_rows, S, n_total, out, sp, st_, mbar); break;
        case 2:  mfe_body<2>(preds, tgt, n_rows, S, n_total, out, sp, st_, mbar); break;
        default: mfe_body<3>(preds, tgt, n_rows, S, n_total, out, sp, st_, mbar); break;
    }
}

extern "C" void kernel_launch(void* const* d_in, const int* in_sizes, int n_in,
                              void* d_out, int out_size)
{
    const float4* preds  = (const float4*)d_in[0];
    const int*    tgt    = (const int*)d_in[1];
    const int*    oi_ptr = (const int*)d_in[2];
    float*        out    = (float*)d_out;

    int n_rows = in_sizes[0] / 4;   // B
    long long per_wave = (long long)NBLK * ROWS_PER_STAGE;
    int S = (int)(((long long)n_rows + per_wave - 1) / per_wave);

    mfe_tma_kernel<<<NBLK, NTHR>>>(preds, tgt, oi_ptr, n_rows, S, (float)n_rows, out);
}